// round 6
// baseline (speedup 1.0000x reference)
#include <cuda_runtime.h>

#define B_  512
#define T_  2048
#define I_  33
#define H_  64
#define O_  2
#define BT_ (B_ * T_)

// Packed fp32x2 ops (Blackwell) — only reachable via PTX.
__device__ __forceinline__ void ffma2(float2& d, float2 a, float2 b) {
    asm("fma.rn.f32x2 %0, %1, %2, %0;"
        : "+l"(*reinterpret_cast<unsigned long long*>(&d))
        : "l"(*reinterpret_cast<const unsigned long long*>(&a)),
          "l"(*reinterpret_cast<const unsigned long long*>(&b)));
}
__device__ __forceinline__ float2 fadd2(float2 a, float2 b) {
    float2 r;
    asm("add.rn.f32x2 %0, %1, %2;"
        : "=l"(*reinterpret_cast<unsigned long long*>(&r))
        : "l"(*reinterpret_cast<const unsigned long long*>(&a)),
          "l"(*reinterpret_cast<const unsigned long long*>(&b)));
    return r;
}
__device__ __forceinline__ float ex2a(float x) {
    float y; asm("ex2.approx.f32 %0, %1;" : "=f"(y) : "f"(x)); return y;
}
__device__ __forceinline__ float rcpa(float x) {
    float y; asm("rcp.approx.f32 %0, %1;" : "=f"(y) : "f"(x)); return y;
}
__device__ __forceinline__ float fast_tanh(float x) {
    float ax = fabsf(x);
    float e  = ex2a(-2.8853900817779268f * ax);
    float r  = (1.0f - e) * rcpa(1.0f + e);
    return copysignf(r, x);
}

// ---------------- Phase 1: xW = x @ W_ih^T + b_ih  (into hidden region) ----------------
// 4 rows x 8 outputs per thread; x transposed in smem -> 3 LDS.128 per 16 FFMA2.
#define XT_STRIDE 132   // pad: %4==0 (float4 align), %32==4 (bounded staging conflicts)
__global__ __launch_bounds__(256) void xw_kernel(
    const float* __restrict__ x, const float* __restrict__ W_ih,
    const float* __restrict__ b_ih, float* __restrict__ xw)
{
    __shared__ float Wc[I_ * H_];                 // col-major: Wc[i*64 + j] = W_ih[j][i]
    __shared__ float bsh[H_];
    __shared__ __align__(16) float xt[I_ * XT_STRIDE];   // transposed: xt[i][row]

    int tid = threadIdx.x;
    int og  = tid >> 5;                           // output group (8 outputs), warp-uniform
    int rl4 = (tid & 31) * 4;                     // 4 rows per lane

    for (int e = tid; e < I_ * H_; e += 256) {
        int i = e >> 6, j = e & 63;
        Wc[e] = W_ih[j * I_ + i];
    }
    if (tid < H_) bsh[tid] = b_ih[tid];

    // Stage x transposed: coalesced global read, scattered smem write (one-time).
    const float* xg = x + (size_t)blockIdx.x * 128 * I_;
    #pragma unroll
    for (int q = 0; q < 17; ++q) {
        int idx = tid + q * 256;
        if (idx < 128 * I_) {
            int row = idx / I_;
            int i   = idx - row * I_;
            xt[i * XT_STRIDE + row] = xg[idx];
        }
    }
    __syncthreads();

    // Accumulators: 4 rows x 4 float2 (8 outputs), bias-initialized.
    float2 bloc[4];
    const float2* b2 = (const float2*)(bsh + og * 8);
    #pragma unroll
    for (int q = 0; q < 4; ++q) bloc[q] = b2[q];
    float2 acc[4][4];
    #pragma unroll
    for (int r = 0; r < 4; ++r)
        #pragma unroll
        for (int q = 0; q < 4; ++q) acc[r][q] = bloc[q];

    #pragma unroll 3
    for (int i = 0; i < I_; ++i) {
        float4 xv = *(const float4*)(xt + i * XT_STRIDE + rl4);        // conflict-free
        const float4* wr = (const float4*)(Wc + i * H_ + og * 8);      // uniform broadcast
        float4 w0 = wr[0], w1 = wr[1];
        float2 wp[4] = { make_float2(w0.x, w0.y), make_float2(w0.z, w0.w),
                         make_float2(w1.x, w1.y), make_float2(w1.z, w1.w) };
        float xr[4] = { xv.x, xv.y, xv.z, xv.w };
        #pragma unroll
        for (int r = 0; r < 4; ++r) {
            float2 x2 = make_float2(xr[r], xr[r]);
            #pragma unroll
            for (int q = 0; q < 4; ++q) ffma2(acc[r][q], wp[q], x2);
        }
    }

    size_t rowbase = (size_t)blockIdx.x * 128 + rl4;
    #pragma unroll
    for (int r = 0; r < 4; ++r) {
        float4* op = (float4*)(xw + (rowbase + r) * H_ + og * 8);      // 32B/row -> full sectors
        op[0] = make_float4(acc[r][0].x, acc[r][0].y, acc[r][1].x, acc[r][1].y);
        op[1] = make_float4(acc[r][2].x, acc[r][2].y, acc[r][3].x, acc[r][3].y);
    }
}

// ---------------- Phase 2: recurrence, 2 independent rows interleaved per warp ----------------
// Weights shared across batch rows (no extra weight regs). Row B's issue fills
// row A's LDS/chain/tanh latency. Intra-warp only; one __syncwarp per step.
__global__ __launch_bounds__(64, 1) void rnn_kernel(
    float* __restrict__ hs, const float* __restrict__ h0,
    const float* __restrict__ W_hh, const float* __restrict__ b_hh)
{
    __shared__ __align__(16) float hb[2][2][2][H_];    // [warp][row][buf][64]
    int w = threadIdx.x >> 5;
    int l = threadIdx.x & 31;
    int row0 = blockIdx.x * 4 + w * 2;
    int row1 = row0 + 1;

    // W_hh rows l and l+32 as 32 k-pairs each (128 regs), shared by both batch rows.
    float2 wA[32], wB[32];
    const float4* wra = (const float4*)(W_hh + l * H_);
    const float4* wrb = (const float4*)(W_hh + (l + 32) * H_);
    #pragma unroll
    for (int q = 0; q < 16; ++q) {
        float4 a = wra[q];
        wA[2 * q] = make_float2(a.x, a.y); wA[2 * q + 1] = make_float2(a.z, a.w);
        float4 b = wrb[q];
        wB[2 * q] = make_float2(b.x, b.y); wB[2 * q + 1] = make_float2(b.z, b.w);
    }
    float bA = b_hh[l], bB = b_hh[l + 32];

    hb[w][0][0][l]      = h0[row0 * H_ + l];
    hb[w][0][0][l + 32] = h0[row0 * H_ + l + 32];
    hb[w][1][0][l]      = h0[row1 * H_ + l];
    hb[w][1][0][l + 32] = h0[row1 * H_ + l + 32];

    float* base0 = hs + (size_t)row0 * T_ * H_;
    float* base1 = hs + (size_t)row1 * T_ * H_;
    // prefetch depth 4 per row; bias folded in at load.
    float xA0[4], xB0[4], xA1[4], xB1[4];
    #pragma unroll
    for (int k = 0; k < 4; ++k) {
        xA0[k] = base0[k * H_ + l]      + bA;
        xB0[k] = base0[k * H_ + l + 32] + bB;
        xA1[k] = base1[k * H_ + l]      + bA;
        xB1[k] = base1[k * H_ + l + 32] + bB;
    }
    __syncwarp();

    for (int t = 0; t < T_; t += 4) {
        #pragma unroll
        for (int k = 0; k < 4; ++k) {
            int tt = t + k;
            const float4* hr0 = (const float4*)hb[w][0][tt & 1];
            const float4* hr1 = (const float4*)hb[w][1][tt & 1];
            float* hw0 = hb[w][0][(tt + 1) & 1];
            float* hw1 = hb[w][1][(tt + 1) & 1];

            // 2 chains per output (depth 16), x 2 outputs x 2 rows = 8 float2.
            float2 a0 = make_float2(xA0[k], 0.f), a1 = make_float2(0.f, 0.f);
            float2 c0 = make_float2(xB0[k], 0.f), c1 = make_float2(0.f, 0.f);
            float2 d0 = make_float2(xA1[k], 0.f), d1 = make_float2(0.f, 0.f);
            float2 e0 = make_float2(xB1[k], 0.f), e1 = make_float2(0.f, 0.f);
            #pragma unroll
            for (int q = 0; q < 16; ++q) {
                float4 h40 = hr0[q];
                float2 p0 = make_float2(h40.x, h40.y);
                float2 p1 = make_float2(h40.z, h40.w);
                ffma2(a0, wA[2 * q],     p0);
                ffma2(a1, wA[2 * q + 1], p1);
                ffma2(c0, wB[2 * q],     p0);
                ffma2(c1, wB[2 * q + 1], p1);
                float4 h41 = hr1[q];
                float2 r0 = make_float2(h41.x, h41.y);
                float2 r1 = make_float2(h41.z, h41.w);
                ffma2(d0, wA[2 * q],     r0);
                ffma2(d1, wA[2 * q + 1], r1);
                ffma2(e0, wB[2 * q],     r0);
                ffma2(e1, wB[2 * q + 1], r1);
            }
            float2 sA0 = fadd2(a0, a1), sB0 = fadd2(c0, c1);
            float2 sA1 = fadd2(d0, d1), sB1 = fadd2(e0, e1);
            float hA0 = fast_tanh(sA0.x + sA0.y);
            float hB0 = fast_tanh(sB0.x + sB0.y);
            float hA1 = fast_tanh(sA1.x + sA1.y);
            float hB1 = fast_tanh(sB1.x + sB1.y);

            hw0[l] = hA0;  hw0[l + 32] = hB0;
            hw1[l] = hA1;  hw1[l + 32] = hB1;
            base0[(size_t)tt * H_ + l]      = hA0;       // output writes (off critical path)
            base0[(size_t)tt * H_ + l + 32] = hB0;
            base1[(size_t)tt * H_ + l]      = hA1;
            base1[(size_t)tt * H_ + l + 32] = hB1;

            int tn = tt + 4; if (tn > T_ - 1) tn = T_ - 1;   // clamped loads never consumed
            xA0[k] = base0[(size_t)tn * H_ + l]      + bA;
            xB0[k] = base0[(size_t)tn * H_ + l + 32] + bB;
            xA1[k] = base1[(size_t)tn * H_ + l]      + bA;
            xB1[k] = base1[(size_t)tn * H_ + l + 32] + bB;
            __syncwarp();
        }
    }
}

// ---------------- Phase 3: predictions = hs @ W_ro^T + b_ro ----------------
__global__ __launch_bounds__(256) void pred_kernel(
    const float* __restrict__ hs, const float* __restrict__ W_ro,
    const float* __restrict__ b_ro, float* __restrict__ pred)
{
    __shared__ float w0[H_], w1[H_];
    int tid = threadIdx.x;
    if (tid < H_) { w0[tid] = W_ro[tid]; w1[tid] = W_ro[H_ + tid]; }
    __syncthreads();

    size_t r = (size_t)blockIdx.x * 256 + tid;
    const float4* hp = (const float4*)(hs + r * H_);
    float p0a = 0.f, p0b = 0.f, p1a = 0.f, p1b = 0.f;
    #pragma unroll
    for (int q = 0; q < 16; ++q) {
        float4 h = hp[q];
        p0a += h.x * w0[4 * q]     + h.z * w0[4 * q + 2];
        p0b += h.y * w0[4 * q + 1] + h.w * w0[4 * q + 3];
        p1a += h.x * w1[4 * q]     + h.z * w1[4 * q + 2];
        p1b += h.y * w1[4 * q + 1] + h.w * w1[4 * q + 3];
    }
    ((float2*)pred)[r] = make_float2(p0a + p0b + b_ro[0], p1a + p1b + b_ro[1]);
}

extern "C" void kernel_launch(void* const* d_in, const int* in_sizes, int n_in,
                              void* d_out, int out_size)
{
    const float* x   = (const float*)d_in[0];
    const float* h0  = (const float*)d_in[1];
    const float* Wih = (const float*)d_in[2];
    const float* Whh = (const float*)d_in[3];
    const float* bih = (const float*)d_in[4];
    const float* bhh = (const float*)d_in[5];
    const float* Wro = (const float*)d_in[6];
    const float* bro = (const float*)d_in[7];

    float* out  = (float*)d_out;
    float* pred = out;                               // [B,T,O]
    float* hsb  = out + (size_t)B_ * T_ * O_;        // [B,T,H] — staged xW, overwritten with h

    xw_kernel  <<<BT_ / 128, 256>>>(x, Wih, bih, hsb);
    rnn_kernel <<<B_ / 4,    64>>>(hsb, h0, Whh, bhh);
    pred_kernel<<<BT_ / 256, 256>>>(hsb, Wro, bro, pred);
}

// round 8
// speedup vs baseline: 1.1277x; 1.1277x over previous
#include <cuda_runtime.h>

#define B_  512
#define T_  2048
#define I_  33
#define H_  64
#define O_  2
#define BT_ (B_ * T_)

// Packed fp32x2 ops (Blackwell) — only reachable via PTX.
__device__ __forceinline__ void ffma2(float2& d, float2 a, float2 b) {
    asm("fma.rn.f32x2 %0, %1, %2, %0;"
        : "+l"(*reinterpret_cast<unsigned long long*>(&d))
        : "l"(*reinterpret_cast<const unsigned long long*>(&a)),
          "l"(*reinterpret_cast<const unsigned long long*>(&b)));
}
__device__ __forceinline__ float2 fadd2(float2 a, float2 b) {
    float2 r;
    asm("add.rn.f32x2 %0, %1, %2;"
        : "=l"(*reinterpret_cast<unsigned long long*>(&r))
        : "l"(*reinterpret_cast<const unsigned long long*>(&a)),
          "l"(*reinterpret_cast<const unsigned long long*>(&b)));
    return r;
}
__device__ __forceinline__ float ex2a(float x) {
    float y; asm("ex2.approx.f32 %0, %1;" : "=f"(y) : "f"(x)); return y;
}
__device__ __forceinline__ float rcpa(float x) {
    float y; asm("rcp.approx.f32 %0, %1;" : "=f"(y) : "f"(x)); return y;
}
__device__ __forceinline__ float fast_tanh(float x) {
    float ax = fabsf(x);
    float e  = ex2a(-2.8853900817779268f * ax);
    float r  = (1.0f - e) * rcpa(1.0f + e);
    return copysignf(r, x);
}

// ---------------- Phase 1: xW = x @ W_ih^T + b_ih  (into hidden region) ----------------
// 4 rows x 8 outputs per thread; x transposed in smem -> 3 LDS.128 per 16 FFMA2.
#define XT_STRIDE 132   // pad: %4==0 (float4 align), %32==4 (bounded staging conflicts)
__global__ __launch_bounds__(256) void xw_kernel(
    const float* __restrict__ x, const float* __restrict__ W_ih,
    const float* __restrict__ b_ih, float* __restrict__ xw)
{
    __shared__ float Wc[I_ * H_];                 // col-major: Wc[i*64 + j] = W_ih[j][i]
    __shared__ float bsh[H_];
    __shared__ __align__(16) float xt[I_ * XT_STRIDE];   // transposed: xt[i][row]

    int tid = threadIdx.x;
    int og  = tid >> 5;                           // output group (8 outputs), warp-uniform
    int rl4 = (tid & 31) * 4;                     // 4 rows per lane

    for (int e = tid; e < I_ * H_; e += 256) {
        int i = e >> 6, j = e & 63;
        Wc[e] = W_ih[j * I_ + i];
    }
    if (tid < H_) bsh[tid] = b_ih[tid];

    // Stage x transposed: coalesced global read, scattered smem write (one-time).
    const float* xg = x + (size_t)blockIdx.x * 128 * I_;
    #pragma unroll
    for (int q = 0; q < 17; ++q) {
        int idx = tid + q * 256;
        if (idx < 128 * I_) {
            int row = idx / I_;
            int i   = idx - row * I_;
            xt[i * XT_STRIDE + row] = xg[idx];
        }
    }
    __syncthreads();

    // Accumulators: 4 rows x 4 float2 (8 outputs), bias-initialized.
    float2 bloc[4];
    const float2* b2 = (const float2*)(bsh + og * 8);
    #pragma unroll
    for (int q = 0; q < 4; ++q) bloc[q] = b2[q];
    float2 acc[4][4];
    #pragma unroll
    for (int r = 0; r < 4; ++r)
        #pragma unroll
        for (int q = 0; q < 4; ++q) acc[r][q] = bloc[q];

    #pragma unroll 3
    for (int i = 0; i < I_; ++i) {
        float4 xv = *(const float4*)(xt + i * XT_STRIDE + rl4);        // conflict-free
        const float4* wr = (const float4*)(Wc + i * H_ + og * 8);      // uniform broadcast
        float4 w0 = wr[0], w1 = wr[1];
        float2 wp[4] = { make_float2(w0.x, w0.y), make_float2(w0.z, w0.w),
                         make_float2(w1.x, w1.y), make_float2(w1.z, w1.w) };
        float xr[4] = { xv.x, xv.y, xv.z, xv.w };
        #pragma unroll
        for (int r = 0; r < 4; ++r) {
            float2 x2 = make_float2(xr[r], xr[r]);
            #pragma unroll
            for (int q = 0; q < 4; ++q) ffma2(acc[r][q], wp[q], x2);
        }
    }

    size_t rowbase = (size_t)blockIdx.x * 128 + rl4;
    #pragma unroll
    for (int r = 0; r < 4; ++r) {
        float4* op = (float4*)(xw + (rowbase + r) * H_ + og * 8);      // 32B/row -> full sectors
        op[0] = make_float4(acc[r][0].x, acc[r][0].y, acc[r][1].x, acc[r][1].y);
        op[1] = make_float4(acc[r][2].x, acc[r][2].y, acc[r][3].x, acc[r][3].y);
    }
}

// ---------------- Phase 2: recurrence, 1 warp per batch row, 8 warps/CTA ----------------
// R5 body (proven ~610us at 1 warp/SMSP), relaunched at 2 warps/SMSP so the
// arbiter overlaps two independent rows' latency. No extra registers (R6 lesson).
__global__ __launch_bounds__(256, 1) void rnn_kernel(
    float* __restrict__ hs, const float* __restrict__ h0,
    const float* __restrict__ W_hh, const float* __restrict__ b_hh)
{
    __shared__ __align__(16) float hb[8][2][H_];
    int w = threadIdx.x >> 5;
    int l = threadIdx.x & 31;
    int row = blockIdx.x * 8 + w;

    // W_hh rows l and l+32 as 32 k-pairs each (128 regs).
    float2 wA[32], wB[32];
    const float4* wra = (const float4*)(W_hh + l * H_);
    const float4* wrb = (const float4*)(W_hh + (l + 32) * H_);
    #pragma unroll
    for (int q = 0; q < 16; ++q) {
        float4 a = wra[q];
        wA[2 * q] = make_float2(a.x, a.y); wA[2 * q + 1] = make_float2(a.z, a.w);
        float4 b = wrb[q];
        wB[2 * q] = make_float2(b.x, b.y); wB[2 * q + 1] = make_float2(b.z, b.w);
    }
    float bA = b_hh[l], bB = b_hh[l + 32];

    hb[w][0][l]      = h0[row * H_ + l];
    hb[w][0][l + 32] = h0[row * H_ + l + 32];

    float* base = hs + (size_t)row * T_ * H_;
    // prefetch depth 4 vs DRAM latency; bias folded in at load.
    float xA[4], xB[4];
    #pragma unroll
    for (int k = 0; k < 4; ++k) {
        xA[k] = base[k * H_ + l]      + bA;
        xB[k] = base[k * H_ + l + 32] + bB;
    }
    __syncwarp();

    for (int t = 0; t < T_; t += 4) {
        #pragma unroll
        for (int k = 0; k < 4; ++k) {
            int tt = t + k;
            const float4* hr = (const float4*)hb[w][tt & 1];       // uniform LDS.128 broadcast
            float*        hw = hb[w][(tt + 1) & 1];

            // 4 chains per output, depth 8 each.
            float2 a0 = make_float2(xA[k], 0.f), a1 = make_float2(0.f, 0.f);
            float2 a2 = make_float2(0.f, 0.f),   a3 = make_float2(0.f, 0.f);
            float2 c0 = make_float2(xB[k], 0.f), c1 = make_float2(0.f, 0.f);
            float2 c2 = make_float2(0.f, 0.f),   c3 = make_float2(0.f, 0.f);
            #pragma unroll
            for (int q = 0; q < 8; ++q) {
                float4 h4a = hr[2 * q];
                float4 h4b = hr[2 * q + 1];
                float2 p0 = make_float2(h4a.x, h4a.y);
                float2 p1 = make_float2(h4a.z, h4a.w);
                float2 p2 = make_float2(h4b.x, h4b.y);
                float2 p3 = make_float2(h4b.z, h4b.w);
                ffma2(a0, wA[4 * q],     p0);
                ffma2(a1, wA[4 * q + 1], p1);
                ffma2(a2, wA[4 * q + 2], p2);
                ffma2(a3, wA[4 * q + 3], p3);
                ffma2(c0, wB[4 * q],     p0);
                ffma2(c1, wB[4 * q + 1], p1);
                ffma2(c2, wB[4 * q + 2], p2);
                ffma2(c3, wB[4 * q + 3], p3);
            }
            float2 sA = fadd2(fadd2(a0, a1), fadd2(a2, a3));
            float2 sB = fadd2(fadd2(c0, c1), fadd2(c2, c3));
            float hA = fast_tanh(sA.x + sA.y);
            float hB = fast_tanh(sB.x + sB.y);

            hw[l]      = hA;  hw[l + 32] = hB;                      // smem for next step
            base[(size_t)tt * H_ + l]      = hA;                    // output write (off path)
            base[(size_t)tt * H_ + l + 32] = hB;

            int tn = tt + 4; if (tn > T_ - 1) tn = T_ - 1;          // clamped loads never consumed
            xA[k] = base[(size_t)tn * H_ + l]      + bA;
            xB[k] = base[(size_t)tn * H_ + l + 32] + bB;
            __syncwarp();
        }
    }
}

// ---------------- Phase 3: predictions = hs @ W_ro^T + b_ro ----------------
__global__ __launch_bounds__(256) void pred_kernel(
    const float* __restrict__ hs, const float* __restrict__ W_ro,
    const float* __restrict__ b_ro, float* __restrict__ pred)
{
    __shared__ float w0[H_], w1[H_];
    int tid = threadIdx.x;
    if (tid < H_) { w0[tid] = W_ro[tid]; w1[tid] = W_ro[H_ + tid]; }
    __syncthreads();

    size_t r = (size_t)blockIdx.x * 256 + tid;
    const float4* hp = (const float4*)(hs + r * H_);
    float p0a = 0.f, p0b = 0.f, p1a = 0.f, p1b = 0.f;
    #pragma unroll
    for (int q = 0; q < 16; ++q) {
        float4 h = hp[q];
        p0a += h.x * w0[4 * q]     + h.z * w0[4 * q + 2];
        p0b += h.y * w0[4 * q + 1] + h.w * w0[4 * q + 3];
        p1a += h.x * w1[4 * q]     + h.z * w1[4 * q + 2];
        p1b += h.y * w1[4 * q + 1] + h.w * w1[4 * q + 3];
    }
    ((float2*)pred)[r] = make_float2(p0a + p0b + b_ro[0], p1a + p1b + b_ro[1]);
}

extern "C" void kernel_launch(void* const* d_in, const int* in_sizes, int n_in,
                              void* d_out, int out_size)
{
    const float* x   = (const float*)d_in[0];
    const float* h0  = (const float*)d_in[1];
    const float* Wih = (const float*)d_in[2];
    const float* Whh = (const float*)d_in[3];
    const float* bih = (const float*)d_in[4];
    const float* bhh = (const float*)d_in[5];
    const float* Wro = (const float*)d_in[6];
    const float* bro = (const float*)d_in[7];

    float* out  = (float*)d_out;
    float* pred = out;                               // [B,T,O]
    float* hsb  = out + (size_t)B_ * T_ * O_;        // [B,T,H] — staged xW, overwritten with h

    xw_kernel  <<<BT_ / 128, 256>>>(x, Wih, bih, hsb);
    rnn_kernel <<<B_ / 8,    256>>>(hsb, h0, Whh, bhh);
    pred_kernel<<<BT_ / 256, 256>>>(hsb, Wro, bro, pred);
}

// round 9
// speedup vs baseline: 1.1932x; 1.0581x over previous
#include <cuda_runtime.h>

#define B_  512
#define T_  2048
#define I_  33
#define H_  64
#define O_  2
#define BT_ (B_ * T_)

// Packed fp32x2 ops (Blackwell) — only reachable via PTX.
__device__ __forceinline__ void ffma2(float2& d, float2 a, float2 b) {
    asm("fma.rn.f32x2 %0, %1, %2, %0;"
        : "+l"(*reinterpret_cast<unsigned long long*>(&d))
        : "l"(*reinterpret_cast<const unsigned long long*>(&a)),
          "l"(*reinterpret_cast<const unsigned long long*>(&b)));
}
__device__ __forceinline__ float2 fadd2(float2 a, float2 b) {
    float2 r;
    asm("add.rn.f32x2 %0, %1, %2;"
        : "=l"(*reinterpret_cast<unsigned long long*>(&r))
        : "l"(*reinterpret_cast<const unsigned long long*>(&a)),
          "l"(*reinterpret_cast<const unsigned long long*>(&b)));
    return r;
}
__device__ __forceinline__ float ex2a(float x) {
    float y; asm("ex2.approx.f32 %0, %1;" : "=f"(y) : "f"(x)); return y;
}
__device__ __forceinline__ float rcpa(float x) {
    float y; asm("rcp.approx.f32 %0, %1;" : "=f"(y) : "f"(x)); return y;
}
__device__ __forceinline__ float fast_tanh(float x) {
    float ax = fabsf(x);
    float e  = ex2a(-2.8853900817779268f * ax);
    float r  = (1.0f - e) * rcpa(1.0f + e);
    return copysignf(r, x);
}

// ---------------- Phase 1: xW = x @ W_ih^T + b_ih  (into hidden region) ----------------
// 64 rows/CTA, 256 threads: 2 rows x 8 outputs per thread (acc=16 regs -> higher occ).
#define XTS 68   // transposed-x stride: even (float2 align), %32==4 -> bounded staging conflicts
__global__ __launch_bounds__(256) void xw_kernel(
    const float* __restrict__ x, const float* __restrict__ W_ih,
    const float* __restrict__ b_ih, float* __restrict__ xw)
{
    __shared__ float Wc[I_ * H_];                 // col-major: Wc[i*64 + j] = W_ih[j][i]
    __shared__ float bsh[H_];
    __shared__ __align__(16) float xt[I_ * XTS];  // transposed: xt[i][row], 64 rows

    int tid = threadIdx.x;
    int og  = tid >> 5;                           // warp -> 8 outputs (warp-uniform)
    int l   = tid & 31;                           // lane -> rows 2l, 2l+1

    for (int e = tid; e < I_ * H_; e += 256) {
        int i = e >> 6, j = e & 63;
        Wc[e] = W_ih[j * I_ + i];
    }
    if (tid < H_) bsh[tid] = b_ih[tid];

    // Stage x transposed: coalesced global read, one-time scattered smem write.
    const float* xg = x + (size_t)blockIdx.x * 64 * I_;
    #pragma unroll
    for (int q = 0; q < 9; ++q) {
        int idx = tid + q * 256;
        if (idx < 64 * I_) {
            int row = idx / I_;
            int i   = idx - row * I_;
            xt[i * XTS + row] = xg[idx];
        }
    }
    __syncthreads();

    float2 bloc[4];
    const float2* b2 = (const float2*)(bsh + og * 8);
    #pragma unroll
    for (int q = 0; q < 4; ++q) bloc[q] = b2[q];
    float2 acc[2][4];
    #pragma unroll
    for (int r = 0; r < 2; ++r)
        #pragma unroll
        for (int q = 0; q < 4; ++q) acc[r][q] = bloc[q];

    #pragma unroll 3
    for (int i = 0; i < I_; ++i) {
        float2 xv = *(const float2*)(xt + i * XTS + 2 * l);            // conflict-free LDS.64
        const float4* wr = (const float4*)(Wc + i * H_ + og * 8);      // uniform broadcast
        float4 w0 = wr[0], w1 = wr[1];
        float2 wp[4] = { make_float2(w0.x, w0.y), make_float2(w0.z, w0.w),
                         make_float2(w1.x, w1.y), make_float2(w1.z, w1.w) };
        float xr[2] = { xv.x, xv.y };
        #pragma unroll
        for (int r = 0; r < 2; ++r) {
            float2 x2 = make_float2(xr[r], xr[r]);
            #pragma unroll
            for (int q = 0; q < 4; ++q) ffma2(acc[r][q], wp[q], x2);
        }
    }

    size_t rowbase = (size_t)blockIdx.x * 64 + 2 * l;
    #pragma unroll
    for (int r = 0; r < 2; ++r) {
        float4* op = (float4*)(xw + (rowbase + r) * H_ + og * 8);
        op[0] = make_float4(acc[r][0].x, acc[r][0].y, acc[r][1].x, acc[r][1].y);
        op[1] = make_float4(acc[r][2].x, acc[r][2].y, acc[r][3].x, acc[r][3].y);
    }
}

// ---------------- Phase 2: recurrence, 1 warp/row, paired outputs j=2l,2l+1 ----------------
// R5 launch shape (128 CTAs x 4 warps = 1 warp/SMSP on 128 SMs — proven best).
// Paired lane map merges x-load (LDG.64), bias (fadd2), h-store (STS.64) and
// output (STG.64) into single ops; 2 accumulation chains per output.
__global__ __launch_bounds__(128, 1) void rnn_kernel(
    float* __restrict__ hs, const float* __restrict__ h0,
    const float* __restrict__ W_hh, const float* __restrict__ b_hh)
{
    __shared__ __align__(16) float hb[4][2][H_];
    int w = threadIdx.x >> 5;
    int l = threadIdx.x & 31;
    int row = blockIdx.x * 4 + w;

    // W_hh rows 2l and 2l+1 as 32 k-pairs each (128 regs).
    float2 wA[32], wB[32];
    const float4* wra = (const float4*)(W_hh + (2 * l)     * H_);
    const float4* wrb = (const float4*)(W_hh + (2 * l + 1) * H_);
    #pragma unroll
    for (int q = 0; q < 16; ++q) {
        float4 a = wra[q];
        wA[2 * q] = make_float2(a.x, a.y); wA[2 * q + 1] = make_float2(a.z, a.w);
        float4 b = wrb[q];
        wB[2 * q] = make_float2(b.x, b.y); wB[2 * q + 1] = make_float2(b.z, b.w);
    }
    float2 bp = ((const float2*)b_hh)[l];

    ((float2*)hb[w][0])[l] = ((const float2*)(h0 + row * H_))[l];

    float* base = hs + (size_t)row * T_ * H_;
    float2 xp[4];                                  // prefetch depth 4, bias folded
    #pragma unroll
    for (int k = 0; k < 4; ++k)
        xp[k] = fadd2(((const float2*)(base + k * H_))[l], bp);
    __syncwarp();

    for (int t = 0; t < T_; t += 4) {
        #pragma unroll
        for (int k = 0; k < 4; ++k) {
            int tt = t + k;
            const float4* hr = (const float4*)hb[w][tt & 1];   // uniform LDS.128 broadcast
            float*        hw = hb[w][(tt + 1) & 1];

            // Seed accumulators with x+b, then issue next prefetch early (off-path LDG.64).
            float2 aA0 = make_float2(xp[k].x, 0.f), aA1 = make_float2(0.f, 0.f);
            float2 aB0 = make_float2(xp[k].y, 0.f), aB1 = make_float2(0.f, 0.f);
            int tn = tt + 4; if (tn > T_ - 1) tn = T_ - 1;      // clamped loads never consumed
            xp[k] = fadd2(((const float2*)(base + (size_t)tn * H_))[l], bp);

            #pragma unroll
            for (int q = 0; q < 16; ++q) {
                float4 h4 = hr[q];
                float2 p0 = make_float2(h4.x, h4.y);
                float2 p1 = make_float2(h4.z, h4.w);
                ffma2(aA0, wA[2 * q],     p0);
                ffma2(aA1, wA[2 * q + 1], p1);
                ffma2(aB0, wB[2 * q],     p0);
                ffma2(aB1, wB[2 * q + 1], p1);
            }
            float2 sA = fadd2(aA0, aA1);
            float2 sB = fadd2(aB0, aB1);
            float hA = fast_tanh(sA.x + sA.y);
            float hB = fast_tanh(sB.x + sB.y);

            float2 hv = make_float2(hA, hB);
            ((float2*)hw)[l] = hv;                              // STS.64 for next step
            ((float2*)(base + (size_t)tt * H_))[l] = hv;        // STG.64 output (off path)
            __syncwarp();
        }
    }
}

// ---------------- Phase 3: predictions = hs @ W_ro^T + b_ro ----------------
__global__ __launch_bounds__(256) void pred_kernel(
    const float* __restrict__ hs, const float* __restrict__ W_ro,
    const float* __restrict__ b_ro, float* __restrict__ pred)
{
    __shared__ float w0[H_], w1[H_];
    int tid = threadIdx.x;
    if (tid < H_) { w0[tid] = W_ro[tid]; w1[tid] = W_ro[H_ + tid]; }
    __syncthreads();

    size_t r = (size_t)blockIdx.x * 256 + tid;
    const float4* hp = (const float4*)(hs + r * H_);
    float p0a = 0.f, p0b = 0.f, p1a = 0.f, p1b = 0.f;
    #pragma unroll
    for (int q = 0; q < 16; ++q) {
        float4 h = hp[q];
        p0a += h.x * w0[4 * q]     + h.z * w0[4 * q + 2];
        p0b += h.y * w0[4 * q + 1] + h.w * w0[4 * q + 3];
        p1a += h.x * w1[4 * q]     + h.z * w1[4 * q + 2];
        p1b += h.y * w1[4 * q + 1] + h.w * w1[4 * q + 3];
    }
    ((float2*)pred)[r] = make_float2(p0a + p0b + b_ro[0], p1a + p1b + b_ro[1]);
}

extern "C" void kernel_launch(void* const* d_in, const int* in_sizes, int n_in,
                              void* d_out, int out_size)
{
    const float* x   = (const float*)d_in[0];
    const float* h0  = (const float*)d_in[1];
    const float* Wih = (const float*)d_in[2];
    const float* Whh = (const float*)d_in[3];
    const float* bih = (const float*)d_in[4];
    const float* bhh = (const float*)d_in[5];
    const float* Wro = (const float*)d_in[6];
    const float* bro = (const float*)d_in[7];

    float* out  = (float*)d_out;
    float* pred = out;                               // [B,T,O]
    float* hsb  = out + (size_t)B_ * T_ * O_;        // [B,T,H] — staged xW, overwritten with h

    xw_kernel  <<<BT_ / 64,  256>>>(x, Wih, bih, hsb);
    rnn_kernel <<<B_ / 4,    128>>>(hsb, h0, Whh, bhh);
    pred_kernel<<<BT_ / 256, 256>>>(hsb, Wro, bro, pred);
}

// round 10
// speedup vs baseline: 1.3654x; 1.1443x over previous
#include <cuda_runtime.h>

#define B_  512
#define T_  2048
#define I_  33
#define H_  64
#define O_  2
#define BT_ (B_ * T_)

// Packed fp32x2 ops (Blackwell) — only reachable via PTX.
__device__ __forceinline__ void ffma2(float2& d, float2 a, float2 b) {
    asm("fma.rn.f32x2 %0, %1, %2, %0;"
        : "+l"(*reinterpret_cast<unsigned long long*>(&d))
        : "l"(*reinterpret_cast<const unsigned long long*>(&a)),
          "l"(*reinterpret_cast<const unsigned long long*>(&b)));
}
__device__ __forceinline__ float2 fadd2(float2 a, float2 b) {
    float2 r;
    asm("add.rn.f32x2 %0, %1, %2;"
        : "=l"(*reinterpret_cast<unsigned long long*>(&r))
        : "l"(*reinterpret_cast<const unsigned long long*>(&a)),
          "l"(*reinterpret_cast<const unsigned long long*>(&b)));
    return r;
}
__device__ __forceinline__ float ex2a(float x) {
    float y; asm("ex2.approx.f32 %0, %1;" : "=f"(y) : "f"(x)); return y;
}
__device__ __forceinline__ float rcpa(float x) {
    float y; asm("rcp.approx.f32 %0, %1;" : "=f"(y) : "f"(x)); return y;
}
__device__ __forceinline__ float fast_tanh(float x) {
    float ax = fabsf(x);
    float e  = ex2a(-2.8853900817779268f * ax);
    float r  = (1.0f - e) * rcpa(1.0f + e);
    return copysignf(r, x);
}

// ---------------- Phase 1: xW = x @ W_ih^T + b_ih  (into hidden region) ----------------
// R6 version (proven 164us): 4 rows x 8 outputs/thread -> 3 LDS per 16 FFMA2.
#define XT_STRIDE 132   // pad: %4==0 (float4 align), %32==4 (bounded staging conflicts)
__global__ __launch_bounds__(256) void xw_kernel(
    const float* __restrict__ x, const float* __restrict__ W_ih,
    const float* __restrict__ b_ih, float* __restrict__ xw)
{
    __shared__ float Wc[I_ * H_];                 // col-major: Wc[i*64 + j] = W_ih[j][i]
    __shared__ float bsh[H_];
    __shared__ __align__(16) float xt[I_ * XT_STRIDE];   // transposed: xt[i][row]

    int tid = threadIdx.x;
    int og  = tid >> 5;                           // output group (8 outputs), warp-uniform
    int rl4 = (tid & 31) * 4;                     // 4 rows per lane

    for (int e = tid; e < I_ * H_; e += 256) {
        int i = e >> 6, j = e & 63;
        Wc[e] = W_ih[j * I_ + i];
    }
    if (tid < H_) bsh[tid] = b_ih[tid];

    const float* xg = x + (size_t)blockIdx.x * 128 * I_;
    #pragma unroll
    for (int q = 0; q < 17; ++q) {
        int idx = tid + q * 256;
        if (idx < 128 * I_) {
            int row = idx / I_;
            int i   = idx - row * I_;
            xt[i * XT_STRIDE + row] = xg[idx];
        }
    }
    __syncthreads();

    float2 bloc[4];
    const float2* b2 = (const float2*)(bsh + og * 8);
    #pragma unroll
    for (int q = 0; q < 4; ++q) bloc[q] = b2[q];
    float2 acc[4][4];
    #pragma unroll
    for (int r = 0; r < 4; ++r)
        #pragma unroll
        for (int q = 0; q < 4; ++q) acc[r][q] = bloc[q];

    #pragma unroll 3
    for (int i = 0; i < I_; ++i) {
        float4 xv = *(const float4*)(xt + i * XT_STRIDE + rl4);        // conflict-free
        const float4* wr = (const float4*)(Wc + i * H_ + og * 8);      // uniform broadcast
        float4 w0 = wr[0], w1 = wr[1];
        float2 wp[4] = { make_float2(w0.x, w0.y), make_float2(w0.z, w0.w),
                         make_float2(w1.x, w1.y), make_float2(w1.z, w1.w) };
        float xr[4] = { xv.x, xv.y, xv.z, xv.w };
        #pragma unroll
        for (int r = 0; r < 4; ++r) {
            float2 x2 = make_float2(xr[r], xr[r]);
            #pragma unroll
            for (int q = 0; q < 4; ++q) ffma2(acc[r][q], wp[q], x2);
        }
    }

    size_t rowbase = (size_t)blockIdx.x * 128 + rl4;
    #pragma unroll
    for (int r = 0; r < 4; ++r) {
        float4* op = (float4*)(xw + (rowbase + r) * H_ + og * 8);
        op[0] = make_float4(acc[r][0].x, acc[r][0].y, acc[r][1].x, acc[r][1].y);
        op[1] = make_float4(acc[r][2].x, acc[r][2].y, acc[r][3].x, acc[r][3].y);
    }
}

// ---------------- Phase 2: recurrence, 1 warp/row, paired outputs j=2l,2l+1 ----------------
// 128 CTAs x 4 warps = 1 warp/SMSP on 128 SMs (proven best shape).
// Paired lane map: 1 LDG.64 prefetch (RAW, bias deferred), 1 STS.64, 1 STG.64 per step.
// Bias add happens at consume time, 4 steps after the load -> no scoreboard stall.
__global__ __launch_bounds__(128, 1) void rnn_kernel(
    float* __restrict__ hs, const float* __restrict__ h0,
    const float* __restrict__ W_hh, const float* __restrict__ b_hh)
{
    __shared__ __align__(16) float hb[4][2][H_];
    int w = threadIdx.x >> 5;
    int l = threadIdx.x & 31;
    int row = blockIdx.x * 4 + w;

    // W_hh rows 2l and 2l+1 as 32 k-pairs each (128 regs).
    float2 wA[32], wB[32];
    const float4* wra = (const float4*)(W_hh + (2 * l)     * H_);
    const float4* wrb = (const float4*)(W_hh + (2 * l + 1) * H_);
    #pragma unroll
    for (int q = 0; q < 16; ++q) {
        float4 a = wra[q];
        wA[2 * q] = make_float2(a.x, a.y); wA[2 * q + 1] = make_float2(a.z, a.w);
        float4 b = wrb[q];
        wB[2 * q] = make_float2(b.x, b.y); wB[2 * q + 1] = make_float2(b.z, b.w);
    }
    float2 bp = ((const float2*)b_hh)[l];

    ((float2*)hb[w][0])[l] = ((const float2*)(h0 + row * H_))[l];

    float* base = hs + (size_t)row * T_ * H_;
    float2 xp[4];                                  // prefetch depth 4, RAW (no bias yet)
    #pragma unroll
    for (int k = 0; k < 4; ++k)
        xp[k] = ((const float2*)(base + k * H_))[l];
    __syncwarp();

    for (int t = 0; t < T_; t += 4) {
        #pragma unroll
        for (int k = 0; k < 4; ++k) {
            int tt = t + k;
            const float4* hr = (const float4*)hb[w][tt & 1];   // uniform LDS.128 broadcast
            float*        hw = hb[w][(tt + 1) & 1];

            // Consume 4-step-old prefetch (load long complete): bias add costs 4 cyc.
            float2 xb = fadd2(xp[k], bp);
            float2 aA0 = make_float2(xb.x, 0.f), aA1 = make_float2(0.f, 0.f);
            float2 aB0 = make_float2(xb.y, 0.f), aB1 = make_float2(0.f, 0.f);
            // Re-issue prefetch for t+4; NOT consumed this step -> stall-free.
            int tn = tt + 4; if (tn > T_ - 1) tn = T_ - 1;      // clamped loads never consumed
            xp[k] = ((const float2*)(base + (size_t)tn * H_))[l];

            #pragma unroll
            for (int q = 0; q < 16; ++q) {
                float4 h4 = hr[q];
                float2 p0 = make_float2(h4.x, h4.y);
                float2 p1 = make_float2(h4.z, h4.w);
                ffma2(aA0, wA[2 * q],     p0);
                ffma2(aA1, wA[2 * q + 1], p1);
                ffma2(aB0, wB[2 * q],     p0);
                ffma2(aB1, wB[2 * q + 1], p1);
            }
            float2 sA = fadd2(aA0, aA1);
            float2 sB = fadd2(aB0, aB1);
            float hA = fast_tanh(sA.x + sA.y);
            float hB = fast_tanh(sB.x + sB.y);

            float2 hv = make_float2(hA, hB);
            ((float2*)hw)[l] = hv;                              // STS.64 for next step
            ((float2*)(base + (size_t)tt * H_))[l] = hv;        // STG.64 output (off path)
            __syncwarp();
        }
    }
}

// ---------------- Phase 3: predictions = hs @ W_ro^T + b_ro ----------------
__global__ __launch_bounds__(256) void pred_kernel(
    const float* __restrict__ hs, const float* __restrict__ W_ro,
    const float* __restrict__ b_ro, float* __restrict__ pred)
{
    __shared__ float w0[H_], w1[H_];
    int tid = threadIdx.x;
    if (tid < H_) { w0[tid] = W_ro[tid]; w1[tid] = W_ro[H_ + tid]; }
    __syncthreads();

    size_t r = (size_t)blockIdx.x * 256 + tid;
    const float4* hp = (const float4*)(hs + r * H_);
    float p0a = 0.f, p0b = 0.f, p1a = 0.f, p1b = 0.f;
    #pragma unroll
    for (int q = 0; q < 16; ++q) {
        float4 h = hp[q];
        p0a += h.x * w0[4 * q]     + h.z * w0[4 * q + 2];
        p0b += h.y * w0[4 * q + 1] + h.w * w0[4 * q + 3];
        p1a += h.x * w1[4 * q]     + h.z * w1[4 * q + 2];
        p1b += h.y * w1[4 * q + 1] + h.w * w1[4 * q + 3];
    }
    ((float2*)pred)[r] = make_float2(p0a + p0b + b_ro[0], p1a + p1b + b_ro[1]);
}

extern "C" void kernel_launch(void* const* d_in, const int* in_sizes, int n_in,
                              void* d_out, int out_size)
{
    const float* x   = (const float*)d_in[0];
    const float* h0  = (const float*)d_in[1];
    const float* Wih = (const float*)d_in[2];
    const float* Whh = (const float*)d_in[3];
    const float* bih = (const float*)d_in[4];
    const float* bhh = (const float*)d_in[5];
    const float* Wro = (const float*)d_in[6];
    const float* bro = (const float*)d_in[7];

    float* out  = (float*)d_out;
    float* pred = out;                               // [B,T,O]
    float* hsb  = out + (size_t)B_ * T_ * O_;        // [B,T,H] — staged xW, overwritten with h

    xw_kernel  <<<BT_ / 128, 256>>>(x, Wih, bih, hsb);
    rnn_kernel <<<B_ / 4,    128>>>(hsb, h0, Whh, bhh);
    pred_kernel<<<BT_ / 256, 256>>>(hsb, Wro, bro, pred);
}

// round 11
// speedup vs baseline: 1.3913x; 1.0189x over previous
#include <cuda_runtime.h>

#define B_  512
#define T_  2048
#define I_  33
#define H_  64
#define O_  2
#define BT_ (B_ * T_)

// Packed fp32x2 ops (Blackwell) — only reachable via PTX.
__device__ __forceinline__ void ffma2(float2& d, float2 a, float2 b) {
    asm("fma.rn.f32x2 %0, %1, %2, %0;"
        : "+l"(*reinterpret_cast<unsigned long long*>(&d))
        : "l"(*reinterpret_cast<const unsigned long long*>(&a)),
          "l"(*reinterpret_cast<const unsigned long long*>(&b)));
}
__device__ __forceinline__ float2 fadd2(float2 a, float2 b) {
    float2 r;
    asm("add.rn.f32x2 %0, %1, %2;"
        : "=l"(*reinterpret_cast<unsigned long long*>(&r))
        : "l"(*reinterpret_cast<const unsigned long long*>(&a)),
          "l"(*reinterpret_cast<const unsigned long long*>(&b)));
    return r;
}
__device__ __forceinline__ float ex2a(float x) {
    float y; asm("ex2.approx.f32 %0, %1;" : "=f"(y) : "f"(x)); return y;
}
__device__ __forceinline__ float rcpa(float x) {
    float y; asm("rcp.approx.f32 %0, %1;" : "=f"(y) : "f"(x)); return y;
}
__device__ __forceinline__ float fast_tanh(float x) {
    float ax = fabsf(x);
    float e  = ex2a(-2.8853900817779268f * ax);
    float r  = (1.0f - e) * rcpa(1.0f + e);
    return copysignf(r, x);
}

// ---------------- Phase 1: xW = x @ W_ih^T + b_ih  (into hidden region) ----------------
// R6 body (proven 164us) + minBlocks=4 to force <=64 regs -> 4 blocks/SM.
#define XT_STRIDE 132   // pad: %4==0 (float4 align), %32==4 (bounded staging conflicts)
__global__ __launch_bounds__(256, 4) void xw_kernel(
    const float* __restrict__ x, const float* __restrict__ W_ih,
    const float* __restrict__ b_ih, float* __restrict__ xw)
{
    __shared__ float Wc[I_ * H_];                 // col-major: Wc[i*64 + j] = W_ih[j][i]
    __shared__ float bsh[H_];
    __shared__ __align__(16) float xt[I_ * XT_STRIDE];   // transposed: xt[i][row]

    int tid = threadIdx.x;
    int og  = tid >> 5;                           // output group (8 outputs), warp-uniform
    int rl4 = (tid & 31) * 4;                     // 4 rows per lane

    for (int e = tid; e < I_ * H_; e += 256) {
        int i = e >> 6, j = e & 63;
        Wc[e] = W_ih[j * I_ + i];
    }
    if (tid < H_) bsh[tid] = b_ih[tid];

    const float* xg = x + (size_t)blockIdx.x * 128 * I_;
    #pragma unroll
    for (int q = 0; q < 17; ++q) {
        int idx = tid + q * 256;
        if (idx < 128 * I_) {
            int row = idx / I_;
            int i   = idx - row * I_;
            xt[i * XT_STRIDE + row] = xg[idx];
        }
    }
    __syncthreads();

    float2 bloc[4];
    const float2* b2 = (const float2*)(bsh + og * 8);
    #pragma unroll
    for (int q = 0; q < 4; ++q) bloc[q] = b2[q];
    float2 acc[4][4];
    #pragma unroll
    for (int r = 0; r < 4; ++r)
        #pragma unroll
        for (int q = 0; q < 4; ++q) acc[r][q] = bloc[q];

    #pragma unroll 3
    for (int i = 0; i < I_; ++i) {
        float4 xv = *(const float4*)(xt + i * XT_STRIDE + rl4);        // conflict-free
        const float4* wr = (const float4*)(Wc + i * H_ + og * 8);      // uniform broadcast
        float4 w0 = wr[0], w1 = wr[1];
        float2 wp[4] = { make_float2(w0.x, w0.y), make_float2(w0.z, w0.w),
                         make_float2(w1.x, w1.y), make_float2(w1.z, w1.w) };
        float xr[4] = { xv.x, xv.y, xv.z, xv.w };
        #pragma unroll
        for (int r = 0; r < 4; ++r) {
            float2 x2 = make_float2(xr[r], xr[r]);
            #pragma unroll
            for (int q = 0; q < 4; ++q) ffma2(acc[r][q], wp[q], x2);
        }
    }

    size_t rowbase = (size_t)blockIdx.x * 128 + rl4;
    #pragma unroll
    for (int r = 0; r < 4; ++r) {
        float4* op = (float4*)(xw + (rowbase + r) * H_ + og * 8);
        op[0] = make_float4(acc[r][0].x, acc[r][0].y, acc[r][1].x, acc[r][1].y);
        op[1] = make_float4(acc[r][2].x, acc[r][2].y, acc[r][3].x, acc[r][3].y);
    }
}

// ---------------- Phase 2: recurrence, 2 warps per row, 1 output per lane ----------------
// 128 CTAs x 8 warps -> 2 warps/SMSP on 128 SMs (R8: 83% overlap at 2/SMSP).
// Warp = one half (32 outputs); lane = one output row of W_hh (64 weight regs).
// Pair exchanges h via double-buffered smem + one named bar.sync(64)/step; the
// barrier latency is hidden by the co-resident warp of ANOTHER pair (fixes R3).
__global__ __launch_bounds__(256, 1) void rnn_kernel(
    float* __restrict__ hs, const float* __restrict__ h0,
    const float* __restrict__ W_hh, const float* __restrict__ b_hh)
{
    __shared__ __align__(16) float hb[4][2][H_];   // [pair][buf][64]
    int wid  = threadIdx.x >> 5;
    int l    = threadIdx.x & 31;
    int pair = wid >> 1;
    int half = wid & 1;
    int row  = blockIdx.x * 4 + pair;
    int j    = half * 32 + l;                      // this lane's output index

    // W_hh row j as 32 k-pairs (64 regs).
    float2 w[32];
    const float4* wr = (const float4*)(W_hh + j * H_);
    #pragma unroll
    for (int q = 0; q < 16; ++q) {
        float4 a = wr[q];
        w[2 * q]     = make_float2(a.x, a.y);
        w[2 * q + 1] = make_float2(a.z, a.w);
    }
    float bj = b_hh[j];

    hb[pair][0][j] = h0[row * H_ + j];

    float* base = hs + (size_t)row * T_ * H_;
    float xp[4];                                   // prefetch depth 4, RAW (bias deferred)
    #pragma unroll
    for (int k = 0; k < 4; ++k)
        xp[k] = base[k * H_ + j];
    __syncthreads();                               // h0 halves visible across the pair

    int barid = pair + 1;                          // named barriers 1..4, 64 threads each
    for (int t = 0; t < T_; t += 4) {
        #pragma unroll
        for (int k = 0; k < 4; ++k) {
            int tt = t + k;
            const float4* hr = (const float4*)hb[pair][tt & 1];    // uniform LDS.128 broadcast
            float*        hw = hb[pair][(tt + 1) & 1];

            // Consume 4-step-old prefetch (long complete); bias add off scoreboard.
            float xb = xp[k] + bj;
            float2 a0 = make_float2(xb, 0.f), a1 = make_float2(0.f, 0.f);
            float2 a2 = make_float2(0.f, 0.f), a3 = make_float2(0.f, 0.f);
            int tn = tt + 4; if (tn > T_ - 1) tn = T_ - 1;         // clamped loads never consumed
            xp[k] = base[(size_t)tn * H_ + j];                     // re-issue prefetch (off path)

            #pragma unroll
            for (int q = 0; q < 8; ++q) {                          // 32 FFMA2, 4 chains depth 8
                float4 h4a = hr[2 * q];
                float4 h4b = hr[2 * q + 1];
                ffma2(a0, w[4 * q],     make_float2(h4a.x, h4a.y));
                ffma2(a1, w[4 * q + 1], make_float2(h4a.z, h4a.w));
                ffma2(a2, w[4 * q + 2], make_float2(h4b.x, h4b.y));
                ffma2(a3, w[4 * q + 3], make_float2(h4b.z, h4b.w));
            }
            float2 s = fadd2(fadd2(a0, a1), fadd2(a2, a3));
            float hn = fast_tanh(s.x + s.y);

            hw[j] = hn;                                            // STS.32 into next buffer
            base[(size_t)tt * H_ + j] = hn;                        // STG.32 output (off path)
            asm volatile("bar.sync %0, 64;" :: "r"(barid) : "memory");
        }
    }
}

// ---------------- Phase 3: predictions = hs @ W_ro^T + b_ro ----------------
__global__ __launch_bounds__(256) void pred_kernel(
    const float* __restrict__ hs, const float* __restrict__ W_ro,
    const float* __restrict__ b_ro, float* __restrict__ pred)
{
    __shared__ float w0[H_], w1[H_];
    int tid = threadIdx.x;
    if (tid < H_) { w0[tid] = W_ro[tid]; w1[tid] = W_ro[H_ + tid]; }
    __syncthreads();

    size_t r = (size_t)blockIdx.x * 256 + tid;
    const float4* hp = (const float4*)(hs + r * H_);
    float p0a = 0.f, p0b = 0.f, p1a = 0.f, p1b = 0.f;
    #pragma unroll
    for (int q = 0; q < 16; ++q) {
        float4 h = hp[q];
        p0a += h.x * w0[4 * q]     + h.z * w0[4 * q + 2];
        p0b += h.y * w0[4 * q + 1] + h.w * w0[4 * q + 3];
        p1a += h.x * w1[4 * q]     + h.z * w1[4 * q + 2];
        p1b += h.y * w1[4 * q + 1] + h.w * w1[4 * q + 3];
    }
    ((float2*)pred)[r] = make_float2(p0a + p0b + b_ro[0], p1a + p1b + b_ro[1]);
}

extern "C" void kernel_launch(void* const* d_in, const int* in_sizes, int n_in,
                              void* d_out, int out_size)
{
    const float* x   = (const float*)d_in[0];
    const float* h0  = (const float*)d_in[1];
    const float* Wih = (const float*)d_in[2];
    const float* Whh = (const float*)d_in[3];
    const float* bih = (const float*)d_in[4];
    const float* bhh = (const float*)d_in[5];
    const float* Wro = (const float*)d_in[6];
    const float* bro = (const float*)d_in[7];

    float* out  = (float*)d_out;
    float* pred = out;                               // [B,T,O]
    float* hsb  = out + (size_t)B_ * T_ * O_;        // [B,T,H] — staged xW, overwritten with h

    xw_kernel  <<<BT_ / 128, 256>>>(x, Wih, bih, hsb);
    rnn_kernel <<<B_ / 4,    256>>>(hsb, h0, Whh, bhh);
    pred_kernel<<<BT_ / 256, 256>>>(hsb, Wro, bro, pred);
}